// round 16
// baseline (speedup 1.0000x reference)
#include <cuda_runtime.h>
#include <cuda_fp16.h>
#include <math.h>
#include <stdint.h>

#define BATCH   4
#define T_SEQ   2048
#define EMB     1024
#define NHEADS  16
#define HDIM    64
#define WHALF   256
#define MTOT    (BATCH * T_SEQ)      // 8192
#define BK      32
#define AROWB   80                   // padded row: 32 fp16 (64B) + 16B pad
#define ASTG    (128 * AROWB)        // A: 128 rows  -> 10240 B
#define BSTG    (64 * AROWB)         // B:  64 rows  ->  5120 B
#define STG     (ASTG + BSTG)        // 15360 B per stage
#define NSTAGE  3                    // 46080 B total -> 4 CTAs/SM

// ---------------------------------------------------------------------------
// Scratch (static device globals; cudaMalloc forbidden)
// ---------------------------------------------------------------------------
__device__ __half a_q [(size_t)MTOT * EMB];   // Xh
__device__ __half a_kv[(size_t)MTOT * EMB];
__device__ __half a_at[(size_t)MTOT * EMB];   // attn out Oh
__device__ __half w_q[EMB * EMB];             // Wh, [N][K] K-major
__device__ __half w_k[EMB * EMB];
__device__ __half w_v[EMB * EMB];
__device__ __half w_o[EMB * EMB];
// attention operands (single fp16)
__device__ __half q2[(size_t)MTOT * NHEADS * 64];   // [m][h][Qh] (x 1/8)
__device__ __half k2[(size_t)MTOT * NHEADS * 64];   // [m][h][Kh]
__device__ __half v2[(size_t)MTOT * EMB];           // [m][h*64+d] Vh
__device__ float g_invf[32];

// ---------------------------------------------------------------------------
// PTX helpers (sm_103 base ISA only)
// ---------------------------------------------------------------------------
#define GDC_WAIT()   asm volatile("griddepcontrol.wait;" ::: "memory")
#define GDC_LAUNCH() asm volatile("griddepcontrol.launch_dependents;" ::: "memory")

__device__ __forceinline__ uint32_t smem_u32(const void* p) {
    uint32_t a;
    asm("{ .reg .u64 t; cvta.to.shared.u64 t, %1; cvt.u32.u64 %0, t; }"
        : "=r"(a) : "l"(p));
    return a;
}
__device__ __forceinline__ void cp16(uint32_t dst, const void* src) {
    asm volatile("cp.async.cg.shared.global [%0], [%1], 16;"
                 :: "r"(dst), "l"(src) : "memory");
}
__device__ __forceinline__ void cp_commit() {
    asm volatile("cp.async.commit_group;" ::: "memory");
}
__device__ __forceinline__ void ldsm4(uint32_t& r0, uint32_t& r1,
                                      uint32_t& r2, uint32_t& r3, uint32_t addr) {
    asm volatile("ldmatrix.sync.aligned.m8n8.x4.shared.b16 {%0,%1,%2,%3}, [%4];"
                 : "=r"(r0), "=r"(r1), "=r"(r2), "=r"(r3) : "r"(addr));
}
__device__ __forceinline__ void ldsm4t(uint32_t& r0, uint32_t& r1,
                                       uint32_t& r2, uint32_t& r3, uint32_t addr) {
    asm volatile("ldmatrix.sync.aligned.m8n8.x4.trans.shared.b16 {%0,%1,%2,%3}, [%4];"
                 : "=r"(r0), "=r"(r1), "=r"(r2), "=r"(r3) : "r"(addr));
}
__device__ __forceinline__ void mma16816(float* c, uint32_t a0, uint32_t a1,
                                         uint32_t a2, uint32_t a3,
                                         uint32_t b0, uint32_t b1) {
    asm volatile(
        "mma.sync.aligned.m16n8k16.row.col.f32.f16.f16.f32 "
        "{%0,%1,%2,%3}, {%4,%5,%6,%7}, {%8,%9}, {%0,%1,%2,%3};"
        : "+f"(c[0]), "+f"(c[1]), "+f"(c[2]), "+f"(c[3])
        : "r"(a0), "r"(a1), "r"(a2), "r"(a3), "r"(b0), "r"(b1));
}
__device__ __forceinline__ uint32_t pk_h2(__half a, __half b) {
    return (uint32_t)__half_as_ushort(a) |
           ((uint32_t)__half_as_ushort(b) << 16);
}
__device__ __forceinline__ uint32_t cvt_h2(float x0, float x1) {
    return pk_h2(__float2half_rn(x0), __float2half_rn(x1));
}

// ---------------------------------------------------------------------------
// Fused conversion kernel: grid (32, 32, 6), 256 threads.
//   z 0/1: inputs Xq/Xkv fp32 -> a_q/a_kv fp16 (MLP-4 batched streaming)
//   z 2-5: weights fp32 [K,N] -> fp16 [N][K]; 64k x 32n tiles, 128B writes.
// ---------------------------------------------------------------------------
__global__ __launch_bounds__(256) void conv_all(
    const float* __restrict__ Xq, const float* __restrict__ Xkv,
    const float* __restrict__ Wq, const float* __restrict__ Wk,
    const float* __restrict__ Wv, const float* __restrict__ Wo)
{
    const int z = blockIdx.z;
    const int t = threadIdx.x;

    if (z < 2) {
        const float* X = z ? Xkv : Xq;
        __half* A = z ? a_kv : a_q;
        const size_t stride = (size_t)32 * 32 * 256;    // 262,144
        const size_t base = (size_t)(blockIdx.y * 32 + blockIdx.x) * 256 + t;
        const float4* X4 = (const float4*)X;
        uint2* A4 = (uint2*)A;
#pragma unroll
        for (int it = 0; it < 2; it++) {
            float4 v[4];
#pragma unroll
            for (int u = 0; u < 4; u++)
                v[u] = X4[base + (size_t)(it * 4 + u) * stride];
#pragma unroll
            for (int u = 0; u < 4; u++) {
                uint2 o;
                o.x = cvt_h2(v[u].x, v[u].y);
                o.y = cvt_h2(v[u].z, v[u].w);
                A4[base + (size_t)(it * 4 + u) * stride] = o;
            }
        }
        GDC_LAUNCH();
        return;
    }

    const int w = z - 2;
    const float* W = (w == 0) ? Wq : (w == 1) ? Wk : (w == 2) ? Wv : Wo;
    __half* O = (w == 0) ? w_q : (w == 1) ? w_k : (w == 2) ? w_v : w_o;

    const int bid = blockIdx.y * 32 + blockIdx.x;
    if (w == 0 && bid == 0 && t < 32)
        g_invf[t] = (float)pow(10000.0, -(double)t / 32.0);
    if (bid >= 512) { GDC_LAUNCH(); return; }   // 16 k-tiles x 32 n-tiles

    const int k0 = (bid & 15) * 64;
    const int n0 = (bid >> 4) * 32;

    __shared__ float tile[64][33];
    const int tx = t & 31, ty = t >> 5;
#pragma unroll
    for (int r = ty; r < 64; r += 8)
        tile[r][tx] = W[(size_t)(k0 + r) * EMB + n0 + tx];
    __syncthreads();
    const int kk = tx * 2;
#pragma unroll
    for (int rn = ty; rn < 32; rn += 8) {
        uint32_t p = cvt_h2(tile[kk][rn], tile[kk + 1][rn]);
        *(uint32_t*)(O + (size_t)(n0 + rn) * EMB + k0 + kk) = p;
    }
    GDC_LAUNCH();
}

// ---------------------------------------------------------------------------
// mma.sync fp16 GEMM, 128x64 CTA tile, 4 warps (2x2 -> 64x32 warp tiles),
// BK=32, 3-stage cp.async, single barrier per chunk, 4 CTAs/SM.
// ---------------------------------------------------------------------------
__global__ __launch_bounds__(128) void mma_gemm(float* __restrict__ Cexp,
                                                int csel_in) {
    const int csel = (csel_in < 0) ? (int)blockIdx.z : csel_in;
    const int rotary = (csel <= 1);
    const __half* Ag = (csel == 0) ? a_q : (csel == 3) ? a_at : a_kv;
    const __half* Bg = (csel == 0) ? w_q : (csel == 1) ? w_k
                       : (csel == 2) ? w_v : w_o;
    const int nch = 32;

    extern __shared__ char smraw[];
    const uint32_t sb = smem_u32(smraw);
    const int t = threadIdx.x;
    const int wid = t >> 5, lane = t & 31;
    const int m0 = blockIdx.y * 128, n0 = blockIdx.x * 64;
    const int wm0 = (wid & 1) * 64;
    const int wn0 = (wid >> 1) * 32;

    const char* Ab = (const char*)(Ag + (size_t)m0 * EMB);
    const char* Bb = (const char*)(Bg + (size_t)n0 * EMB);

#define LOAD_CHUNK(c)                                                          \
    do {                                                                       \
        uint32_t _sa = sb + ((c) % NSTAGE) * STG;                              \
        uint32_t _sb2 = _sa + ASTG;                                            \
        _Pragma("unroll")                                                      \
        for (int _i = 0; _i < 4; _i++) {                                       \
            int _idx = t + _i * 128;                                           \
            int _row = _idx >> 2, _seg = _idx & 3;                             \
            size_t _g = (size_t)_row * (EMB * 2) + (size_t)(c) * 64            \
                        + _seg * 16;                                           \
            cp16(_sa + (uint32_t)(_row * AROWB + _seg * 16), Ab + _g);         \
        }                                                                      \
        _Pragma("unroll")                                                      \
        for (int _i = 0; _i < 2; _i++) {                                       \
            int _idx = t + _i * 128;                                           \
            int _row = _idx >> 2, _seg = _idx & 3;                             \
            size_t _g = (size_t)_row * (EMB * 2) + (size_t)(c) * 64            \
                        + _seg * 16;                                           \
            cp16(_sb2 + (uint32_t)(_row * AROWB + _seg * 16), Bb + _g);        \
        }                                                                      \
        cp_commit();                                                           \
    } while (0)

    float acc[4][4][4];
#pragma unroll
    for (int i = 0; i < 4; i++)
#pragma unroll
        for (int j = 0; j < 4; j++)
#pragma unroll
            for (int u = 0; u < 4; u++) acc[i][j][u] = 0.0f;

    GDC_WAIT();            // producer data (conv / attention) now visible
    LOAD_CHUNK(0);
    LOAD_CHUNK(1);

    const int lq = lane >> 3, lr = lane & 7;
    const int a_row = (lq & 1) * 8 + lr;
    const int a_cb  = (lq >> 1) * 16;
    const int b_row = (lq >> 1) * 8 + lr;
    const int b_cb  = (lq & 1) * 16;

    for (int c = 0; c < nch; c++) {
        if (c >= nch - 1) asm volatile("cp.async.wait_group 0;" ::: "memory");
        else              asm volatile("cp.async.wait_group 1;" ::: "memory");
        __syncthreads();
        if (c + 2 < nch) LOAD_CHUNK(c + 2);

        const uint32_t sa  = sb + (c % NSTAGE) * STG;
        const uint32_t sb2 = sa + ASTG;

#pragma unroll
        for (int ks = 0; ks < 2; ks++) {
            uint32_t af[4][4], bf[2][4];
#pragma unroll
            for (int i = 0; i < 4; i++)
                ldsm4(af[i][0], af[i][1], af[i][2], af[i][3],
                      sa + (uint32_t)((wm0 + i * 16 + a_row) * AROWB
                                      + ks * 32 + a_cb));
#pragma unroll
            for (int jp = 0; jp < 2; jp++)
                ldsm4(bf[jp][0], bf[jp][1], bf[jp][2], bf[jp][3],
                      sb2 + (uint32_t)((wn0 + jp * 16 + b_row) * AROWB
                                       + ks * 32 + b_cb));
#pragma unroll
            for (int i = 0; i < 4; i++)
#pragma unroll
                for (int j = 0; j < 4; j++)
                    mma16816(acc[i][j], af[i][0], af[i][1], af[i][2], af[i][3],
                             bf[j >> 1][(j & 1) * 2], bf[j >> 1][(j & 1) * 2 + 1]);
        }
    }

    // ---- epilogue ----
    const int mrow = lane >> 2;
    const int ncol = (lane & 3) * 2;
#pragma unroll
    for (int i = 0; i < 4; i++) {
        const int gmA = m0 + wm0 + i * 16 + mrow;
        const int gmB = gmA + 8;
        const float tpA = (float)(gmA & (T_SEQ - 1));
        const float tpB = (float)(gmB & (T_SEQ - 1));
#pragma unroll
        for (int j = 0; j < 4; j++) {
            const int gc = n0 + wn0 + j * 8 + ncol;
            float x0 = acc[i][j][0], x1 = acc[i][j][1];
            float y0 = acc[i][j][2], y1 = acc[i][j][3];
            if (rotary) {
                const int p = (gc & 63) >> 1;
                const float f = g_invf[p];
                float angA = __fmul_rn(tpA, f);
                float angB = __fmul_rn(tpB, f);
                double dA = (double)angA;
                double rA = dA - floor(dA * 0.15915494309189535) * 6.283185307179586;
                double dB = (double)angB;
                double rB = dB - floor(dB * 0.15915494309189535) * 6.283185307179586;
                float sA = sinf((float)rA), cA = cosf((float)rA);
                float sB = sinf((float)rB), cB = cosf((float)rB);
                float t0 = x0 * cA - x1 * sA;
                float t1 = x1 * cA + x0 * sA;
                float u0 = y0 * cB - y1 * sB;
                float u1 = y1 * cB + y0 * sB;
                x0 = t0; x1 = t1; y0 = u0; y1 = u1;
            }
            const int hh = gc >> 6, d = gc & 63;
            if (csel == 0 || csel == 1) {
                if (csel == 0) { x0 *= 0.125f; x1 *= 0.125f;
                                 y0 *= 0.125f; y1 *= 0.125f; }
                __half* dst = (csel == 0) ? q2 : k2;
                *(uint32_t*)(dst + ((size_t)gmA * NHEADS + hh) * 64 + d) =
                    cvt_h2(x0, x1);
                *(uint32_t*)(dst + ((size_t)gmB * NHEADS + hh) * 64 + d) =
                    cvt_h2(y0, y1);
            } else if (csel == 2) {
                *(uint32_t*)(v2 + (size_t)gmA * EMB + gc) = cvt_h2(x0, x1);
                *(uint32_t*)(v2 + (size_t)gmB * EMB + gc) = cvt_h2(y0, y1);
            } else {
                *(float2*)(Cexp + (size_t)gmA * EMB + gc) = make_float2(x0, x1);
                *(float2*)(Cexp + (size_t)gmB * EMB + gc) = make_float2(y0, y1);
            }
        }
    }
    GDC_LAUNCH();
#undef LOAD_CHUNK
}

// ---------------------------------------------------------------------------
// Banded flash attention, fp16 mma, cp.async double-buffered K/V prefetch.
// Block = (64 queries, head, batch), 4 warps. One barrier per k-tile.
// ---------------------------------------------------------------------------
#define KPITCH 144                       // 64 fp16 (128B) + 16B pad
#define SM_Q    0                        // 64*144 = 9216
#define SM_KV0  9216                     // stage s at 9216 + s*18432
#define KVSTG   18432                    // K (9216) + V (9216)
#define SM_ATT  (9216 + 2 * KVSTG)       // 46080 bytes

__device__ __forceinline__ void attn_load_kv_nocommit(uint32_t sb, int stage,
                                                      int b, int kbase, int h,
                                                      int t) {
    const uint32_t base = sb + SM_KV0 + stage * KVSTG;
#pragma unroll
    for (int i = 0; i < 4; i++) {
        int idx = t + i * 128;
        int r = idx >> 3, c = idx & 7;
        const char* ks = (const char*)(k2 +
            ((size_t)(b * T_SEQ + kbase + r) * NHEADS + h) * 64) + c * 16;
        const char* vs = (const char*)(v2 +
            (size_t)(b * T_SEQ + kbase + r) * EMB + h * 64) + c * 16;
        cp16(base + (uint32_t)(r * KPITCH + c * 16), ks);
        cp16(base + 9216u + (uint32_t)(r * KPITCH + c * 16), vs);
    }
}

__global__ __launch_bounds__(128) void attn_mma() {
    const int qt = blockIdx.x, h = blockIdx.y, b = blockIdx.z;
    const int t = threadIdx.x;
    const int wid = t >> 5, lane = t & 31;
    const int qbase = qt * 64;

    extern __shared__ char smraw[];
    const uint32_t sb = smem_u32(smraw);

    const int kt_lo = (qt - 4 > 0) ? (qt - 4) : 0;
    const int kt_hi = (qt + 4 < 31) ? (qt + 4) : 31;

    GDC_WAIT();            // q2/k2/v2 from the QKV GEMM now visible

    // ---- Q tile + first K/V tile in ONE cp.async group ----
#pragma unroll
    for (int i = 0; i < 4; i++) {
        int idx = t + i * 128;
        int r = idx >> 3, c = idx & 7;
        const char* qs = (const char*)(q2 +
            ((size_t)(b * T_SEQ + qbase + r) * NHEADS + h) * 64) + c * 16;
        cp16(sb + SM_Q + (uint32_t)(r * KPITCH + c * 16), qs);
    }
    attn_load_kv_nocommit(sb, 0, b, kt_lo * 64, h, t);
    cp_commit();

    float m0r = -3.0e38f, m1r = -3.0e38f, l0r = 0.0f, l1r = 0.0f;
    float o[8][4];
#pragma unroll
    for (int j = 0; j < 8; j++)
#pragma unroll
        for (int u = 0; u < 4; u++) o[j][u] = 0.0f;

    const int r0g = qbase + 16 * wid + (lane >> 2);
    const int coff = 2 * (lane & 3);

    int stage = 0;
    for (int kt = kt_lo; kt <= kt_hi; kt++) {
        const int kbase = kt * 64;
        asm volatile("cp.async.wait_group 0;" ::: "memory");
        __syncthreads();
        if (kt < kt_hi) {
            attn_load_kv_nocommit(sb, stage ^ 1, b, kbase + 64, h, t);
            cp_commit();
        }

        const uint32_t smK = sb + SM_KV0 + stage * KVSTG;
        const uint32_t smV = smK + 9216u;

        float s[8][4];
#pragma unroll
        for (int j = 0; j < 8; j++)
#pragma unroll
            for (int u = 0; u < 4; u++) s[j][u] = 0.0f;

        const uint32_t aAddrBase = sb + SM_Q
            + (uint32_t)((16 * wid + (lane & 15)) * KPITCH + (lane >> 4) * 16);
        const int bRow = (lane & 7) + ((lane >> 4) << 3);
        const uint32_t bAddrBase = smK
            + (uint32_t)(bRow * KPITCH + (((lane >> 3) & 1) << 4));

#pragma unroll
        for (int ks = 0; ks < 4; ks++) {
            uint32_t a0, a1, a2, a3;
            ldsm4(a0, a1, a2, a3, aAddrBase + ks * 32);
#pragma unroll
            for (int g = 0; g < 4; g++) {
                uint32_t b0, b1, b2, b3;
                ldsm4(b0, b1, b2, b3,
                      bAddrBase + (uint32_t)(g * 16 * KPITCH + ks * 32));
                mma16816(s[2 * g],     a0, a1, a2, a3, b0, b1);
                mma16816(s[2 * g + 1], a0, a1, a2, a3, b2, b3);
            }
        }

#pragma unroll
        for (int j = 0; j < 8; j++) {
            int c0 = kbase + 8 * j + coff;
            int d00 = r0g - c0, d01 = r0g - (c0 + 1);
            if (d00 > WHALF || d00 < -WHALF) s[j][0] = -1.0e30f;
            if (d01 > WHALF || d01 < -WHALF) s[j][1] = -1.0e30f;
            int d10 = d00 + 8, d11 = d01 + 8;
            if (d10 > WHALF || d10 < -WHALF) s[j][2] = -1.0e30f;
            if (d11 > WHALF || d11 < -WHALF) s[j][3] = -1.0e30f;
        }

        float mx0 = -1.0e30f, mx1 = -1.0e30f;
#pragma unroll
        for (int j = 0; j < 8; j++) {
            mx0 = fmaxf(mx0, fmaxf(s[j][0], s[j][1]));
            mx1 = fmaxf(mx1, fmaxf(s[j][2], s[j][3]));
        }
        mx0 = fmaxf(mx0, __shfl_xor_sync(0xffffffffu, mx0, 1));
        mx0 = fmaxf(mx0, __shfl_xor_sync(0xffffffffu, mx0, 2));
        mx1 = fmaxf(mx1, __shfl_xor_sync(0xffffffffu, mx1, 1));
        mx1 = fmaxf(mx1, __shfl_xor_sync(0xffffffffu, mx1, 2));
        float mn0 = fmaxf(m0r, mx0), mn1 = fmaxf(m1r, mx1);
        float cor0 = __expf(m0r - mn0), cor1 = __expf(m1r - mn1);
        m0r = mn0; m1r = mn1;

        float rs0 = 0.0f, rs1 = 0.0f;
#pragma unroll
        for (int j = 0; j < 8; j++) {
            s[j][0] = __expf(s[j][0] - mn0);
            s[j][1] = __expf(s[j][1] - mn0);
            s[j][2] = __expf(s[j][2] - mn1);
            s[j][3] = __expf(s[j][3] - mn1);
            rs0 += s[j][0] + s[j][1];
            rs1 += s[j][2] + s[j][3];
        }
        rs0 += __shfl_xor_sync(0xffffffffu, rs0, 1);
        rs0 += __shfl_xor_sync(0xffffffffu, rs0, 2);
        rs1 += __shfl_xor_sync(0xffffffffu, rs1, 1);
        rs1 += __shfl_xor_sync(0xffffffffu, rs1, 2);
        l0r = l0r * cor0 + rs0;
        l1r = l1r * cor1 + rs1;

#pragma unroll
        for (int j = 0; j < 8; j++) {
            o[j][0] *= cor0; o[j][1] *= cor0;
            o[j][2] *= cor1; o[j][3] *= cor1;
        }

        uint32_t ph[4][4];
#pragma unroll
        for (int ks2 = 0; ks2 < 4; ks2++) {
            int j0 = 2 * ks2, j1 = j0 + 1;
            ph[ks2][0] = cvt_h2(s[j0][0], s[j0][1]);
            ph[ks2][1] = cvt_h2(s[j0][2], s[j0][3]);
            ph[ks2][2] = cvt_h2(s[j1][0], s[j1][1]);
            ph[ks2][3] = cvt_h2(s[j1][2], s[j1][3]);
        }

        const uint32_t vAddrBase = smV
            + (uint32_t)((lane & 15) * KPITCH + (lane >> 4) * 16);
#pragma unroll
        for (int ks2 = 0; ks2 < 4; ks2++) {
            uint32_t voff = vAddrBase + (uint32_t)(ks2 * 16 * KPITCH);
#pragma unroll
            for (int g = 0; g < 4; g++) {
                uint32_t v0, v1, v2r, v3;
                ldsm4t(v0, v1, v2r, v3, voff + g * 32);
                mma16816(o[2 * g],     ph[ks2][0], ph[ks2][1], ph[ks2][2],
                         ph[ks2][3], v0, v1);
                mma16816(o[2 * g + 1], ph[ks2][0], ph[ks2][1], ph[ks2][2],
                         ph[ks2][3], v2r, v3);
            }
        }
        stage ^= 1;
    }

    const float inv0 = 1.0f / l0r, inv1 = 1.0f / l1r;
    const size_t mA = (size_t)(b * T_SEQ) + qbase + 16 * wid + (lane >> 2);
    const size_t mB = mA + 8;
    __half* rowA = a_at + mA * EMB + h * 64 + coff;
    __half* rowB = a_at + mB * EMB + h * 64 + coff;
#pragma unroll
    for (int j = 0; j < 8; j++) {
        *(uint32_t*)(rowA + 8 * j) = cvt_h2(o[j][0] * inv0, o[j][1] * inv0);
        *(uint32_t*)(rowB + 8 * j) = cvt_h2(o[j][2] * inv1, o[j][3] * inv1);
    }
    GDC_LAUNCH();
}

// ---------------------------------------------------------------------------
// Launch — 4 launches, chained with programmatic dependent launch (PDL)
// ---------------------------------------------------------------------------
static void launch_pdl(void* fn, dim3 grid, dim3 block, size_t smem,
                       void** args) {
    cudaLaunchConfig_t cfg = {};
    cfg.gridDim = grid;
    cfg.blockDim = block;
    cfg.dynamicSmemBytes = smem;
    cfg.stream = 0;
    cudaLaunchAttribute attr[1];
    attr[0].id = cudaLaunchAttributeProgrammaticStreamSerialization;
    attr[0].val.programmaticStreamSerializationAllowed = 1;
    cfg.attrs = attr;
    cfg.numAttrs = 1;
    cudaLaunchKernelExC(&cfg, fn, args);
}

extern "C" void kernel_launch(void* const* d_in, const int* in_sizes, int n_in,
                              void* d_out, int out_size)
{
    const float* xq  = (const float*)d_in[0];
    const float* xkv = (const float*)d_in[1];
    const float* Wq  = (const float*)d_in[2];
    const float* Wk  = (const float*)d_in[3];
    const float* Wv  = (const float*)d_in[4];
    const float* Wo  = (const float*)d_in[5];
    float* out = (float*)d_out;

    conv_all<<<dim3(32, 32, 6), 256>>>(xq, xkv, Wq, Wk, Wv, Wo);

    const int gemm_smem = NSTAGE * STG;   // 46080
    cudaFuncSetAttribute(mma_gemm, cudaFuncAttributeMaxDynamicSharedMemorySize,
                         gemm_smem);
    cudaFuncSetAttribute(attn_mma, cudaFuncAttributeMaxDynamicSharedMemorySize,
                         SM_ATT);

    {   // QKV projections (depends on conv_all)
        float* cz = nullptr; int cs = -1;
        void* args[2] = { &cz, &cs };
        launch_pdl((void*)mma_gemm, dim3(EMB / 64, MTOT / 128, 3),
                   dim3(128, 1, 1), gemm_smem, args);
    }
    {   // attention (depends on QKV GEMM)
        void* args[1] = { nullptr };
        launch_pdl((void*)attn_mma, dim3(T_SEQ / 64, NHEADS, BATCH),
                   dim3(128, 1, 1), SM_ATT, (void**)args);
    }
    {   // O-projection (depends on attention)
        float* co = out; int cs = 3;
        void* args[2] = { &co, &cs };
        launch_pdl((void*)mma_gemm, dim3(EMB / 64, MTOT / 128, 1),
                   dim3(128, 1, 1), gemm_smem, args);
    }
}

// round 17
// speedup vs baseline: 1.1205x; 1.1205x over previous
#include <cuda_runtime.h>
#include <cuda_fp16.h>
#include <math.h>
#include <stdint.h>

#define BATCH   4
#define T_SEQ   2048
#define EMB     1024
#define NHEADS  16
#define HDIM    64
#define WHALF   256
#define MTOT    (BATCH * T_SEQ)      // 8192
#define BK      64
#define AROWB   144                  // padded row: 64 fp16 (128B) + 16B pad
#define ASTG    (128 * AROWB)        // A: 128 rows -> 18432 B
#define BSTG    (64 * AROWB)         // B:  64 rows ->  9216 B
#define STG     (ASTG + BSTG)        // 27648 B per stage
#define NSTAGE  2                    // 55296 B total -> 4 CTAs/SM

// ---------------------------------------------------------------------------
// Scratch (static device globals; cudaMalloc forbidden)
// ---------------------------------------------------------------------------
__device__ __half a_q [(size_t)MTOT * EMB];   // Xh
__device__ __half a_kv[(size_t)MTOT * EMB];
__device__ __half a_at[(size_t)MTOT * EMB];   // attn out Oh
__device__ __half w_q[EMB * EMB];             // Wh, [N][K] K-major
__device__ __half w_k[EMB * EMB];
__device__ __half w_v[EMB * EMB];
__device__ __half w_o[EMB * EMB];
// attention operands (single fp16)
__device__ __half q2[(size_t)MTOT * NHEADS * 64];   // [m][h][Qh] (x 1/8)
__device__ __half k2[(size_t)MTOT * NHEADS * 64];   // [m][h][Kh]
__device__ __half v2[(size_t)MTOT * EMB];           // [m][h*64+d] Vh
__device__ float g_invf[32];

// ---------------------------------------------------------------------------
// PTX helpers (sm_103 base ISA only)
// ---------------------------------------------------------------------------
__device__ __forceinline__ uint32_t smem_u32(const void* p) {
    uint32_t a;
    asm("{ .reg .u64 t; cvta.to.shared.u64 t, %1; cvt.u32.u64 %0, t; }"
        : "=r"(a) : "l"(p));
    return a;
}
__device__ __forceinline__ void cp16(uint32_t dst, const void* src) {
    asm volatile("cp.async.cg.shared.global [%0], [%1], 16;"
                 :: "r"(dst), "l"(src) : "memory");
}
__device__ __forceinline__ void cp_commit() {
    asm volatile("cp.async.commit_group;" ::: "memory");
}
__device__ __forceinline__ void ldsm4(uint32_t& r0, uint32_t& r1,
                                      uint32_t& r2, uint32_t& r3, uint32_t addr) {
    asm volatile("ldmatrix.sync.aligned.m8n8.x4.shared.b16 {%0,%1,%2,%3}, [%4];"
                 : "=r"(r0), "=r"(r1), "=r"(r2), "=r"(r3) : "r"(addr));
}
__device__ __forceinline__ void ldsm4t(uint32_t& r0, uint32_t& r1,
                                       uint32_t& r2, uint32_t& r3, uint32_t addr) {
    asm volatile("ldmatrix.sync.aligned.m8n8.x4.trans.shared.b16 {%0,%1,%2,%3}, [%4];"
                 : "=r"(r0), "=r"(r1), "=r"(r2), "=r"(r3) : "r"(addr));
}
__device__ __forceinline__ void mma16816(float* c, uint32_t a0, uint32_t a1,
                                         uint32_t a2, uint32_t a3,
                                         uint32_t b0, uint32_t b1) {
    asm volatile(
        "mma.sync.aligned.m16n8k16.row.col.f32.f16.f16.f32 "
        "{%0,%1,%2,%3}, {%4,%5,%6,%7}, {%8,%9}, {%0,%1,%2,%3};"
        : "+f"(c[0]), "+f"(c[1]), "+f"(c[2]), "+f"(c[3])
        : "r"(a0), "r"(a1), "r"(a2), "r"(a3), "r"(b0), "r"(b1));
}
__device__ __forceinline__ uint32_t pk_h2(__half a, __half b) {
    return (uint32_t)__half_as_ushort(a) |
           ((uint32_t)__half_as_ushort(b) << 16);
}
__device__ __forceinline__ uint32_t cvt_h2(float x0, float x1) {
    return pk_h2(__float2half_rn(x0), __float2half_rn(x1));
}

// ---------------------------------------------------------------------------
// Fused conversion kernel: grid (32, 32, 6), 256 threads.
// ---------------------------------------------------------------------------
__global__ __launch_bounds__(256) void conv_all(
    const float* __restrict__ Xq, const float* __restrict__ Xkv,
    const float* __restrict__ Wq, const float* __restrict__ Wk,
    const float* __restrict__ Wv, const float* __restrict__ Wo)
{
    const int z = blockIdx.z;
    const int t = threadIdx.x;

    if (z < 2) {
        const float* X = z ? Xkv : Xq;
        __half* A = z ? a_kv : a_q;
        const size_t stride = (size_t)32 * 32 * 256;    // 262,144
        const size_t base = (size_t)(blockIdx.y * 32 + blockIdx.x) * 256 + t;
        const float4* X4 = (const float4*)X;
        uint2* A4 = (uint2*)A;
#pragma unroll
        for (int it = 0; it < 2; it++) {
            float4 v[4];
#pragma unroll
            for (int u = 0; u < 4; u++)
                v[u] = X4[base + (size_t)(it * 4 + u) * stride];
#pragma unroll
            for (int u = 0; u < 4; u++) {
                uint2 o;
                o.x = cvt_h2(v[u].x, v[u].y);
                o.y = cvt_h2(v[u].z, v[u].w);
                A4[base + (size_t)(it * 4 + u) * stride] = o;
            }
        }
        return;
    }

    const int w = z - 2;
    const float* W = (w == 0) ? Wq : (w == 1) ? Wk : (w == 2) ? Wv : Wo;
    __half* O = (w == 0) ? w_q : (w == 1) ? w_k : (w == 2) ? w_v : w_o;

    const int bid = blockIdx.y * 32 + blockIdx.x;
    if (w == 0 && bid == 0 && t < 32)
        g_invf[t] = (float)pow(10000.0, -(double)t / 32.0);
    if (bid >= 512) return;                 // 16 k-tiles x 32 n-tiles

    const int k0 = (bid & 15) * 64;
    const int n0 = (bid >> 4) * 32;

    __shared__ float tile[64][33];
    const int tx = t & 31, ty = t >> 5;
#pragma unroll
    for (int r = ty; r < 64; r += 8)
        tile[r][tx] = W[(size_t)(k0 + r) * EMB + n0 + tx];
    __syncthreads();
    const int kk = tx * 2;
#pragma unroll
    for (int rn = ty; rn < 32; rn += 8) {
        uint32_t p = cvt_h2(tile[kk][rn], tile[kk + 1][rn]);
        *(uint32_t*)(O + (size_t)(n0 + rn) * EMB + k0 + kk) = p;
    }
}

// ---------------------------------------------------------------------------
// mma.sync fp16 GEMM, 128x64 CTA tile, 4 warps (2x2 -> 64x32 warp tiles),
// BK=64 (16 chunks), 2-stage cp.async, single barrier per chunk, 4 CTAs/SM.
// Same k-accumulation order as BK=32 -> bit-identical results.
// ---------------------------------------------------------------------------
__global__ __launch_bounds__(128) void mma_gemm(float* __restrict__ Cexp,
                                                int csel_in) {
    const int csel = (csel_in < 0) ? (int)blockIdx.z : csel_in;
    const int rotary = (csel <= 1);
    const __half* Ag = (csel == 0) ? a_q : (csel == 3) ? a_at : a_kv;
    const __half* Bg = (csel == 0) ? w_q : (csel == 1) ? w_k
                       : (csel == 2) ? w_v : w_o;
    const int nch = 16;

    extern __shared__ char smraw[];
    const uint32_t sb = smem_u32(smraw);
    const int t = threadIdx.x;
    const int wid = t >> 5, lane = t & 31;
    const int m0 = blockIdx.y * 128, n0 = blockIdx.x * 64;
    const int wm0 = (wid & 1) * 64;
    const int wn0 = (wid >> 1) * 32;

    const char* Ab = (const char*)(Ag + (size_t)m0 * EMB);
    const char* Bb = (const char*)(Bg + (size_t)n0 * EMB);

    // A: 128 rows x 8 segs(16B) = 1024 slots -> 8/thread
    // B:  64 rows x 8 segs     =  512 slots -> 4/thread
#define LOAD_CHUNK(c)                                                          \
    do {                                                                       \
        uint32_t _sa = sb + ((c) & 1) * STG;                                   \
        uint32_t _sb2 = _sa + ASTG;                                            \
        _Pragma("unroll")                                                      \
        for (int _i = 0; _i < 8; _i++) {                                       \
            int _idx = t + _i * 128;                                           \
            int _row = _idx >> 3, _seg = _idx & 7;                             \
            size_t _g = (size_t)_row * (EMB * 2) + (size_t)(c) * 128           \
                        + _seg * 16;                                           \
            cp16(_sa + (uint32_t)(_row * AROWB + _seg * 16), Ab + _g);         \
        }                                                                      \
        _Pragma("unroll")                                                      \
        for (int _i = 0; _i < 4; _i++) {                                       \
            int _idx = t + _i * 128;                                           \
            int _row = _idx >> 3, _seg = _idx & 7;                             \
            size_t _g = (size_t)_row * (EMB * 2) + (size_t)(c) * 128           \
                        + _seg * 16;                                           \
            cp16(_sb2 + (uint32_t)(_row * AROWB + _seg * 16), Bb + _g);        \
        }                                                                      \
        cp_commit();                                                           \
    } while (0)

    float acc[4][4][4];
#pragma unroll
    for (int i = 0; i < 4; i++)
#pragma unroll
        for (int j = 0; j < 4; j++)
#pragma unroll
            for (int u = 0; u < 4; u++) acc[i][j][u] = 0.0f;

    LOAD_CHUNK(0);

    const int lq = lane >> 3, lr = lane & 7;
    const int a_row = (lq & 1) * 8 + lr;
    const int a_cb  = (lq >> 1) * 16;
    const int b_row = (lq >> 1) * 8 + lr;
    const int b_cb  = (lq & 1) * 16;

    for (int c = 0; c < nch; c++) {
        asm volatile("cp.async.wait_group 0;" ::: "memory");
        __syncthreads();   // chunk c resident; stage (c+1)&1 reads finished
        if (c + 1 < nch) LOAD_CHUNK(c + 1);

        const uint32_t sa  = sb + (c & 1) * STG;
        const uint32_t sb2 = sa + ASTG;

#pragma unroll
        for (int ks = 0; ks < 4; ks++) {
            uint32_t af[4][4], bf[2][4];
#pragma unroll
            for (int i = 0; i < 4; i++)
                ldsm4(af[i][0], af[i][1], af[i][2], af[i][3],
                      sa + (uint32_t)((wm0 + i * 16 + a_row) * AROWB
                                      + ks * 32 + a_cb));
#pragma unroll
            for (int jp = 0; jp < 2; jp++)
                ldsm4(bf[jp][0], bf[jp][1], bf[jp][2], bf[jp][3],
                      sb2 + (uint32_t)((wn0 + jp * 16 + b_row) * AROWB
                                       + ks * 32 + b_cb));
#pragma unroll
            for (int i = 0; i < 4; i++)
#pragma unroll
                for (int j = 0; j < 4; j++)
                    mma16816(acc[i][j], af[i][0], af[i][1], af[i][2], af[i][3],
                             bf[j >> 1][(j & 1) * 2], bf[j >> 1][(j & 1) * 2 + 1]);
        }
    }

    // ---- epilogue ----
    const int mrow = lane >> 2;
    const int ncol = (lane & 3) * 2;
#pragma unroll
    for (int i = 0; i < 4; i++) {
        const int gmA = m0 + wm0 + i * 16 + mrow;
        const int gmB = gmA + 8;
        const float tpA = (float)(gmA & (T_SEQ - 1));
        const float tpB = (float)(gmB & (T_SEQ - 1));
#pragma unroll
        for (int j = 0; j < 4; j++) {
            const int gc = n0 + wn0 + j * 8 + ncol;
            float x0 = acc[i][j][0], x1 = acc[i][j][1];
            float y0 = acc[i][j][2], y1 = acc[i][j][3];
            if (rotary) {
                const int p = (gc & 63) >> 1;
                const float f = g_invf[p];
                float angA = __fmul_rn(tpA, f);
                float angB = __fmul_rn(tpB, f);
                double dA = (double)angA;
                double rA = dA - floor(dA * 0.15915494309189535) * 6.283185307179586;
                double dB = (double)angB;
                double rB = dB - floor(dB * 0.15915494309189535) * 6.283185307179586;
                float sA = sinf((float)rA), cA = cosf((float)rA);
                float sB = sinf((float)rB), cB = cosf((float)rB);
                float t0 = x0 * cA - x1 * sA;
                float t1 = x1 * cA + x0 * sA;
                float u0 = y0 * cB - y1 * sB;
                float u1 = y1 * cB + y0 * sB;
                x0 = t0; x1 = t1; y0 = u0; y1 = u1;
            }
            const int hh = gc >> 6, d = gc & 63;
            if (csel == 0 || csel == 1) {
                if (csel == 0) { x0 *= 0.125f; x1 *= 0.125f;
                                 y0 *= 0.125f; y1 *= 0.125f; }
                __half* dst = (csel == 0) ? q2 : k2;
                *(uint32_t*)(dst + ((size_t)gmA * NHEADS + hh) * 64 + d) =
                    cvt_h2(x0, x1);
                *(uint32_t*)(dst + ((size_t)gmB * NHEADS + hh) * 64 + d) =
                    cvt_h2(y0, y1);
            } else if (csel == 2) {
                *(uint32_t*)(v2 + (size_t)gmA * EMB + gc) = cvt_h2(x0, x1);
                *(uint32_t*)(v2 + (size_t)gmB * EMB + gc) = cvt_h2(y0, y1);
            } else {
                *(float2*)(Cexp + (size_t)gmA * EMB + gc) = make_float2(x0, x1);
                *(float2*)(Cexp + (size_t)gmB * EMB + gc) = make_float2(y0, y1);
            }
        }
    }
#undef LOAD_CHUNK
}

// ---------------------------------------------------------------------------
// Banded flash attention, fp16 mma, cp.async double-buffered K/V prefetch.
// ---------------------------------------------------------------------------
#define KPITCH 144                       // 64 fp16 (128B) + 16B pad
#define SM_Q    0                        // 64*144 = 9216
#define SM_KV0  9216
#define KVSTG   18432                    // K (9216) + V (9216)
#define SM_ATT  (9216 + 2 * KVSTG)       // 46080 bytes

__device__ __forceinline__ void attn_load_kv_nocommit(uint32_t sb, int stage,
                                                      int b, int kbase, int h,
                                                      int t) {
    const uint32_t base = sb + SM_KV0 + stage * KVSTG;
#pragma unroll
    for (int i = 0; i < 4; i++) {
        int idx = t + i * 128;
        int r = idx >> 3, c = idx & 7;
        const char* ks = (const char*)(k2 +
            ((size_t)(b * T_SEQ + kbase + r) * NHEADS + h) * 64) + c * 16;
        const char* vs = (const char*)(v2 +
            (size_t)(b * T_SEQ + kbase + r) * EMB + h * 64) + c * 16;
        cp16(base + (uint32_t)(r * KPITCH + c * 16), ks);
        cp16(base + 9216u + (uint32_t)(r * KPITCH + c * 16), vs);
    }
}

__global__ __launch_bounds__(128) void attn_mma() {
    const int qt = blockIdx.x, h = blockIdx.y, b = blockIdx.z;
    const int t = threadIdx.x;
    const int wid = t >> 5, lane = t & 31;
    const int qbase = qt * 64;

    extern __shared__ char smraw[];
    const uint32_t sb = smem_u32(smraw);

    const int kt_lo = (qt - 4 > 0) ? (qt - 4) : 0;
    const int kt_hi = (qt + 4 < 31) ? (qt + 4) : 31;

    // ---- Q tile + first K/V tile in ONE cp.async group ----
#pragma unroll
    for (int i = 0; i < 4; i++) {
        int idx = t + i * 128;
        int r = idx >> 3, c = idx & 7;
        const char* qs = (const char*)(q2 +
            ((size_t)(b * T_SEQ + qbase + r) * NHEADS + h) * 64) + c * 16;
        cp16(sb + SM_Q + (uint32_t)(r * KPITCH + c * 16), qs);
    }
    attn_load_kv_nocommit(sb, 0, b, kt_lo * 64, h, t);
    cp_commit();

    float m0r = -3.0e38f, m1r = -3.0e38f, l0r = 0.0f, l1r = 0.0f;
    float o[8][4];
#pragma unroll
    for (int j = 0; j < 8; j++)
#pragma unroll
        for (int u = 0; u < 4; u++) o[j][u] = 0.0f;

    const int r0g = qbase + 16 * wid + (lane >> 2);
    const int coff = 2 * (lane & 3);

    int stage = 0;
    for (int kt = kt_lo; kt <= kt_hi; kt++) {
        const int kbase = kt * 64;
        asm volatile("cp.async.wait_group 0;" ::: "memory");
        __syncthreads();
        if (kt < kt_hi) {
            attn_load_kv_nocommit(sb, stage ^ 1, b, kbase + 64, h, t);
            cp_commit();
        }

        const uint32_t smK = sb + SM_KV0 + stage * KVSTG;
        const uint32_t smV = smK + 9216u;

        float s[8][4];
#pragma unroll
        for (int j = 0; j < 8; j++)
#pragma unroll
            for (int u = 0; u < 4; u++) s[j][u] = 0.0f;

        const uint32_t aAddrBase = sb + SM_Q
            + (uint32_t)((16 * wid + (lane & 15)) * KPITCH + (lane >> 4) * 16);
        const int bRow = (lane & 7) + ((lane >> 4) << 3);
        const uint32_t bAddrBase = smK
            + (uint32_t)(bRow * KPITCH + (((lane >> 3) & 1) << 4));

#pragma unroll
        for (int ks = 0; ks < 4; ks++) {
            uint32_t a0, a1, a2, a3;
            ldsm4(a0, a1, a2, a3, aAddrBase + ks * 32);
#pragma unroll
            for (int g = 0; g < 4; g++) {
                uint32_t b0, b1, b2, b3;
                ldsm4(b0, b1, b2, b3,
                      bAddrBase + (uint32_t)(g * 16 * KPITCH + ks * 32));
                mma16816(s[2 * g],     a0, a1, a2, a3, b0, b1);
                mma16816(s[2 * g + 1], a0, a1, a2, a3, b2, b3);
            }
        }

#pragma unroll
        for (int j = 0; j < 8; j++) {
            int c0 = kbase + 8 * j + coff;
            int d00 = r0g - c0, d01 = r0g - (c0 + 1);
            if (d00 > WHALF || d00 < -WHALF) s[j][0] = -1.0e30f;
            if (d01 > WHALF || d01 < -WHALF) s[j][1] = -1.0e30f;
            int d10 = d00 + 8, d11 = d01 + 8;
            if (d10 > WHALF || d10 < -WHALF) s[j][2] = -1.0e30f;
            if (d11 > WHALF || d11 < -WHALF) s[j][3] = -1.0e30f;
        }

        float mx0 = -1.0e30f, mx1 = -1.0e30f;
#pragma unroll
        for (int j = 0; j < 8; j++) {
            mx0 = fmaxf(mx0, fmaxf(s[j][0], s[j][1]));
            mx1 = fmaxf(mx1, fmaxf(s[j][2], s[j][3]));
        }
        mx0 = fmaxf(mx0, __shfl_xor_sync(0xffffffffu, mx0, 1));
        mx0 = fmaxf(mx0, __shfl_xor_sync(0xffffffffu, mx0, 2));
        mx1 = fmaxf(mx1, __shfl_xor_sync(0xffffffffu, mx1, 1));
        mx1 = fmaxf(mx1, __shfl_xor_sync(0xffffffffu, mx1, 2));
        float mn0 = fmaxf(m0r, mx0), mn1 = fmaxf(m1r, mx1);
        float cor0 = __expf(m0r - mn0), cor1 = __expf(m1r - mn1);
        m0r = mn0; m1r = mn1;

        float rs0 = 0.0f, rs1 = 0.0f;
#pragma unroll
        for (int j = 0; j < 8; j++) {
            s[j][0] = __expf(s[j][0] - mn0);
            s[j][1] = __expf(s[j][1] - mn0);
            s[j][2] = __expf(s[j][2] - mn1);
            s[j][3] = __expf(s[j][3] - mn1);
            rs0 += s[j][0] + s[j][1];
            rs1 += s[j][2] + s[j][3];
        }
        rs0 += __shfl_xor_sync(0xffffffffu, rs0, 1);
        rs0 += __shfl_xor_sync(0xffffffffu, rs0, 2);
        rs1 += __shfl_xor_sync(0xffffffffu, rs1, 1);
        rs1 += __shfl_xor_sync(0xffffffffu, rs1, 2);
        l0r = l0r * cor0 + rs0;
        l1r = l1r * cor1 + rs1;

#pragma unroll
        for (int j = 0; j < 8; j++) {
            o[j][0] *= cor0; o[j][1] *= cor0;
            o[j][2] *= cor1; o[j][3] *= cor1;
        }

        uint32_t ph[4][4];
#pragma unroll
        for (int ks2 = 0; ks2 < 4; ks2++) {
            int j0 = 2 * ks2, j1 = j0 + 1;
            ph[ks2][0] = cvt_h2(s[j0][0], s[j0][1]);
            ph[ks2][1] = cvt_h2(s[j0][2], s[j0][3]);
            ph[ks2][2] = cvt_h2(s[j1][0], s[j1][1]);
            ph[ks2][3] = cvt_h2(s[j1][2], s[j1][3]);
        }

        const uint32_t vAddrBase = smV
            + (uint32_t)((lane & 15) * KPITCH + (lane >> 4) * 16);
#pragma unroll
        for (int ks2 = 0; ks2 < 4; ks2++) {
            uint32_t voff = vAddrBase + (uint32_t)(ks2 * 16 * KPITCH);
#pragma unroll
            for (int g = 0; g < 4; g++) {
                uint32_t v0, v1, v2r, v3;
                ldsm4t(v0, v1, v2r, v3, voff + g * 32);
                mma16816(o[2 * g],     ph[ks2][0], ph[ks2][1], ph[ks2][2],
                         ph[ks2][3], v0, v1);
                mma16816(o[2 * g + 1], ph[ks2][0], ph[ks2][1], ph[ks2][2],
                         ph[ks2][3], v2r, v3);
            }
        }
        stage ^= 1;
    }

    const float inv0 = 1.0f / l0r, inv1 = 1.0f / l1r;
    const size_t mA = (size_t)(b * T_SEQ) + qbase + 16 * wid + (lane >> 2);
    const size_t mB = mA + 8;
    __half* rowA = a_at + mA * EMB + h * 64 + coff;
    __half* rowB = a_at + mB * EMB + h * 64 + coff;
#pragma unroll
    for (int j = 0; j < 8; j++) {
        *(uint32_t*)(rowA + 8 * j) = cvt_h2(o[j][0] * inv0, o[j][1] * inv0);
        *(uint32_t*)(rowB + 8 * j) = cvt_h2(o[j][2] * inv1, o[j][3] * inv1);
    }
}

// ---------------------------------------------------------------------------
// Launch — 4 plain launches (PDL reverted: measured neutral)
// ---------------------------------------------------------------------------
extern "C" void kernel_launch(void* const* d_in, const int* in_sizes, int n_in,
                              void* d_out, int out_size)
{
    const float* xq  = (const float*)d_in[0];
    const float* xkv = (const float*)d_in[1];
    const float* Wq  = (const float*)d_in[2];
    const float* Wk  = (const float*)d_in[3];
    const float* Wv  = (const float*)d_in[4];
    const float* Wo  = (const float*)d_in[5];
    float* out = (float*)d_out;

    conv_all<<<dim3(32, 32, 6), 256>>>(xq, xkv, Wq, Wk, Wv, Wo);

    const int gemm_smem = NSTAGE * STG;   // 55296
    cudaFuncSetAttribute(mma_gemm, cudaFuncAttributeMaxDynamicSharedMemorySize,
                         gemm_smem);

    mma_gemm<<<dim3(EMB / 64, MTOT / 128, 3), 128, gemm_smem>>>(nullptr, -1);

    cudaFuncSetAttribute(attn_mma, cudaFuncAttributeMaxDynamicSharedMemorySize,
                         SM_ATT);
    attn_mma<<<dim3(T_SEQ / 64, NHEADS, BATCH), 128, SM_ATT>>>();

    mma_gemm<<<dim3(EMB / 64, MTOT / 128, 1), 128, gemm_smem>>>(out, 3);
}